// round 17
// baseline (speedup 1.0000x reference)
#include <cuda_runtime.h>
#include <cuda_fp16.h>

// IntDVF scaling-and-squaring, packed-half4, batch-paired + hoisted-load ILP.
// ddf0 = dvf / 2^7 ; repeat 7x: ddf = ddf + warp(ddf, ddf)
//
// Field stored as 4x fp16 (x,y,z,pad) = 8B/voxel (33.5 MB/buffer -> both
// ping-pong buffers L2-resident). Each thread processes the SAME (x,y,z)
// voxel in batch 0 and batch 1. All 16 gather LDG.64s are explicitly hoisted
// ahead of the interpolation math, and __launch_bounds__(256,4) gives ptxas
// 64 regs so the loads genuinely stay in flight (R15: regs=32 serialized them).
// fp32 arithmetic; fp16 storage only. Final step writes fp32 AoS to d_out.

#define D     128
#define D2    (D * D)
#define D3    (D * D * D)
#define NVOX  (2 * D3)          // 4,194,304 voxels (batch=2)
#define NT    256

// Two 33.5 MB packed ping-pong buffers (both L2-resident together).
__device__ uint2 g_a[(size_t)NVOX];
__device__ uint2 g_b[(size_t)NVOX];

__device__ __forceinline__ uint2 packh4(float x, float y, float z) {
    __half2 xy = __floats2half2_rn(x, y);
    __half2 zw = __floats2half2_rn(z, 0.0f);
    uint2 r;
    r.x = *(const unsigned int*)&xy;
    r.y = *(const unsigned int*)&zw;
    return r;
}

__device__ __forceinline__ void unpackh4(uint2 v, float& x, float& y, float& z) {
    __half2 xy = *(const __half2*)&v.x;
    __half2 zw = *(const __half2*)&v.y;
    float2 f = __half22float2(xy);
    x = f.x;
    y = f.y;
    z = __half2float(__low2half(zw));
}

__global__ __launch_bounds__(NT)
void pack_h4(const float* __restrict__ in, uint2* __restrict__ out) {
    int i = blockIdx.x * NT + threadIdx.x;
    size_t o = (size_t)i * 3;
    out[i] = packh4(in[o + 0], in[o + 1], in[o + 2]);
}

struct Tap {
    int r00, r01, r10, r11, offz;
    float w000, w001, w010, w011, w100, w101, w110, w111;
};

template<bool SCALED>
__device__ __forceinline__ Tap make_tap(
    int bb, float xf, float yf, float zf,
    float rx, float ry, float rz, float scale)
{
    float lx = xf + (SCALED ? rx * scale : rx);
    float ly = yf + (SCALED ? ry * scale : ry);
    float lz = zf + (SCALED ? rz * scale : rz);

    // Clamp the location (equivalent to the reference's index clipping).
    lx = fminf(fmaxf(lx, 0.0f), 127.0f);
    ly = fminf(fmaxf(ly, 0.0f), 127.0f);
    lz = fminf(fmaxf(lz, 0.0f), 127.0f);

    float fx = floorf(lx), fy = floorf(ly), fz = floorf(lz);
    float wx1 = lx - fx, wy1 = ly - fy, wz1 = lz - fz;
    float wx0 = 1.0f - wx1, wy0 = 1.0f - wy1, wz0 = 1.0f - wz1;

    int jx = (int)fx, jy = (int)fy, jz = (int)fz;   // all in [0,127]

    int offx = (jx < D - 1) ? D2 : 0;
    int offy = (jy < D - 1) ? D  : 0;

    Tap t;
    t.offz = (jz < D - 1) ? 1 : 0;
    t.r00 = bb + (jx << 14) + (jy << 7) + jz;
    t.r01 = t.r00 + offy;
    t.r10 = t.r00 + offx;
    t.r11 = t.r10 + offy;

    float w00 = wx0 * wy0, w01 = wx0 * wy1, w10 = wx1 * wy0, w11 = wx1 * wy1;
    t.w000 = w00 * wz0; t.w001 = w00 * wz1;
    t.w010 = w01 * wz0; t.w011 = w01 * wz1;
    t.w100 = w10 * wz0; t.w101 = w10 * wz1;
    t.w110 = w11 * wz0; t.w111 = w11 * wz1;
    return t;
}

__device__ __forceinline__ float3 lerp8(const uint2* v, const Tap& t) {
    float ax = 0.f, ay = 0.f, az = 0.f, tx, ty, tz;
    unpackh4(v[0], tx, ty, tz); ax = fmaf(t.w000, tx, ax); ay = fmaf(t.w000, ty, ay); az = fmaf(t.w000, tz, az);
    unpackh4(v[1], tx, ty, tz); ax = fmaf(t.w001, tx, ax); ay = fmaf(t.w001, ty, ay); az = fmaf(t.w001, tz, az);
    unpackh4(v[2], tx, ty, tz); ax = fmaf(t.w010, tx, ax); ay = fmaf(t.w010, ty, ay); az = fmaf(t.w010, tz, az);
    unpackh4(v[3], tx, ty, tz); ax = fmaf(t.w011, tx, ax); ay = fmaf(t.w011, ty, ay); az = fmaf(t.w011, tz, az);
    unpackh4(v[4], tx, ty, tz); ax = fmaf(t.w100, tx, ax); ay = fmaf(t.w100, ty, ay); az = fmaf(t.w100, tz, az);
    unpackh4(v[5], tx, ty, tz); ax = fmaf(t.w101, tx, ax); ay = fmaf(t.w101, ty, ay); az = fmaf(t.w101, tz, az);
    unpackh4(v[6], tx, ty, tz); ax = fmaf(t.w110, tx, ax); ay = fmaf(t.w110, ty, ay); az = fmaf(t.w110, tz, az);
    unpackh4(v[7], tx, ty, tz); ax = fmaf(t.w111, tx, ax); ay = fmaf(t.w111, ty, ay); az = fmaf(t.w111, tz, az);
    return make_float3(ax, ay, az);
}

template<bool OUT_F32_AOS, bool SCALED>
__global__ __launch_bounds__(NT, 4)      // allow 64 regs/thread
void intdvf_step(const uint2* __restrict__ src, void* __restrict__ dst_raw,
                 float scale) {
    int idx0 = blockIdx.x * NT + threadIdx.x;   // batch-0 voxel
    int idx1 = idx0 + D3;                       // same (x,y,z), batch 1
    int z = idx0 & (D - 1);
    int y = (idx0 >> 7) & (D - 1);
    int x = idx0 >> 14;                         // idx0 < D3 -> b=0

    float xf = (float)x, yf = (float)y, zf = (float)z;

    // Both center reads up front.
    uint2 c0 = __ldg(src + idx0);
    uint2 c1 = __ldg(src + idx1);
    float rx0, ry0, rz0, rx1, ry1, rz1;
    unpackh4(c0, rx0, ry0, rz0);
    unpackh4(c1, rx1, ry1, rz1);

    Tap t0 = make_tap<SCALED>(0,  xf, yf, zf, rx0, ry0, rz0, scale);
    Tap t1 = make_tap<SCALED>(D3, xf, yf, zf, rx1, ry1, rz1, scale);

    // Hoist ALL 16 gather loads before any interpolation math (MLP=16).
    uint2 v0[8], v1[8];
    v0[0] = __ldg(src + t0.r00);
    v0[1] = __ldg(src + t0.r00 + t0.offz);
    v0[2] = __ldg(src + t0.r01);
    v0[3] = __ldg(src + t0.r01 + t0.offz);
    v0[4] = __ldg(src + t0.r10);
    v0[5] = __ldg(src + t0.r10 + t0.offz);
    v0[6] = __ldg(src + t0.r11);
    v0[7] = __ldg(src + t0.r11 + t0.offz);
    v1[0] = __ldg(src + t1.r00);
    v1[1] = __ldg(src + t1.r00 + t1.offz);
    v1[2] = __ldg(src + t1.r01);
    v1[3] = __ldg(src + t1.r01 + t1.offz);
    v1[4] = __ldg(src + t1.r10);
    v1[5] = __ldg(src + t1.r10 + t1.offz);
    v1[6] = __ldg(src + t1.r11);
    v1[7] = __ldg(src + t1.r11 + t1.offz);

    float3 a0 = lerp8(v0, t0);
    float3 a1 = lerp8(v1, t1);

    float ox0, oy0, oz0, ox1, oy1, oz1;
    if (SCALED) {
        ox0 = scale * (rx0 + a0.x); oy0 = scale * (ry0 + a0.y); oz0 = scale * (rz0 + a0.z);
        ox1 = scale * (rx1 + a1.x); oy1 = scale * (ry1 + a1.y); oz1 = scale * (rz1 + a1.z);
    } else {
        ox0 = rx0 + a0.x; oy0 = ry0 + a0.y; oz0 = rz0 + a0.z;
        ox1 = rx1 + a1.x; oy1 = ry1 + a1.y; oz1 = rz1 + a1.z;
    }

    if (OUT_F32_AOS) {
        float* dst = (float*)dst_raw;
        size_t o0 = (size_t)idx0 * 3;
        size_t o1 = (size_t)idx1 * 3;
        dst[o0 + 0] = ox0; dst[o0 + 1] = oy0; dst[o0 + 2] = oz0;
        dst[o1 + 0] = ox1; dst[o1 + 1] = oy1; dst[o1 + 2] = oz1;
    } else {
        uint2* d2 = (uint2*)dst_raw;
        d2[idx0] = packh4(ox0, oy0, oz0);
        d2[idx1] = packh4(ox1, oy1, oz1);
    }
}

extern "C" void kernel_launch(void* const* d_in, const int* in_sizes, int n_in,
                              void* d_out, int out_size) {
    const float* dvf = (const float*)d_in[0];

    uint2* A = nullptr;
    uint2* Bf = nullptr;
    cudaGetSymbolAddress((void**)&A,  g_a);
    cudaGetSymbolAddress((void**)&Bf, g_b);

    const int pack_blocks = NVOX / NT;          // 16384
    const int step_blocks = D3 / NT;            // 8192 (2 voxels/thread)
    const float s0 = 1.0f / 128.0f;             // 1 / 2^NUM_STEPS

    pack_h4<<<pack_blocks, NT>>>(dvf, A);

    intdvf_step<false, true ><<<step_blocks, NT>>>(A,  Bf,   s0);   // step 1 (fused /128)
    intdvf_step<false, false><<<step_blocks, NT>>>(Bf, A,    1.0f); // step 2
    intdvf_step<false, false><<<step_blocks, NT>>>(A,  Bf,   1.0f); // step 3
    intdvf_step<false, false><<<step_blocks, NT>>>(Bf, A,    1.0f); // step 4
    intdvf_step<false, false><<<step_blocks, NT>>>(A,  Bf,   1.0f); // step 5
    intdvf_step<false, false><<<step_blocks, NT>>>(Bf, A,    1.0f); // step 6
    intdvf_step<true,  false><<<step_blocks, NT>>>(A,  d_out, 1.0f); // step 7 -> fp32 AoS
}